// round 3
// baseline (speedup 1.0000x reference)
#include <cuda_runtime.h>
#include <math.h>

typedef unsigned long long u64;

#define NB 8
#define NM 4
#define NT 2048
#define NE 768
#define NP 256
#define NKD 64
#define NVD 64
#define NH 128
#define NX 16
#define NCOMB 384
#define NMLP 192
#define NTOK (NB*NM*NT)   /* 65536 */

// ---------------- scratch ----------------------------------------------------
__device__ float g_processed[(size_t)NTOK*NP];
__device__ float g_hid[(size_t)NTOK*NMLP];
__device__ float g_scal[(size_t)NTOK*2];
__device__ float g_rus[(size_t)NTOK*NH];
__device__ float g_wa[NP], g_wb[NP], g_wc[NP];
__device__ float g_cc[3];
__device__ float g_c0[3*NH], g_c1[3*NH], g_c2[3*NH], g_c3[3*NH];

// ---------------- f32x2 helpers ---------------------------------------------
__device__ __forceinline__ u64 ffma2(u64 a, u64 b, u64 c) {
    u64 d;
    asm("fma.rn.f32x2 %0, %1, %2, %3;" : "=l"(d) : "l"(a), "l"(b), "l"(c));
    return d;
}
__device__ __forceinline__ u64 pack2(float x, float y) {
    u64 d;
    asm("mov.b64 %0, {%1, %2};" : "=l"(d) : "f"(x), "f"(y));
    return d;
}
__device__ __forceinline__ float lo2(u64 v) { return __uint_as_float((unsigned)v); }
__device__ __forceinline__ float hi2(u64 v) { return __uint_as_float((unsigned)(v >> 32)); }

// ---------------- precompute folded weight vectors ---------------------------
__global__ void __launch_bounds__(384) k_pre(
                      const float* __restrict__ qw, const float* __restrict__ qb,
                      const float* __restrict__ kw, const float* __restrict__ kb,
                      const float* __restrict__ wih, const float* __restrict__ bih,
                      const float* __restrict__ vw, const float* __restrict__ vb) {
    int i = threadIdx.x;
    if (i < NP) {
        float a = 0.f, b = 0.f, c = 0.f;
#pragma unroll 4
        for (int k = 0; k < NKD; k++) {
            float q = qw[k*NP + i];
            a = fmaf(q, kw[2*k], a);
            b = fmaf(q, kw[2*k+1], b);
            c = fmaf(q, kb[k], c);
        }
        g_wa[i] = a; g_wb[i] = b; g_wc[i] = c;
    }
    if (i == 0) {
        float a = 0.f, b = 0.f, c = 0.f;
#pragma unroll 4
        for (int k = 0; k < NKD; k++) {
            float q = qb[k];
            a = fmaf(q, kw[2*k], a);
            b = fmaf(q, kw[2*k+1], b);
            c = fmaf(q, kb[k], c);
        }
        g_cc[0] = a; g_cc[1] = b; g_cc[2] = c;
    }
    if (i < 3*NH) {
        const float* wr = wih + (size_t)i*(1 + NVD);
        float c1 = 0.f, c2 = 0.f, c3 = bih[i];
#pragma unroll 4
        for (int v = 0; v < NVD; v++) {
            float w = wr[1 + v];
            c1 = fmaf(w, vw[2*v], c1);
            c2 = fmaf(w, vw[2*v+1], c2);
            c3 = fmaf(w, vb[v], c3);
        }
        g_c0[i] = wr[0]; g_c1[i] = c1; g_c2[i] = c2; g_c3[i] = c3;
    }
}

// ============================================================================
// SGEMM: C[.. x N] = op(A[M x K] @ W[N x K]^T (+bias) (+C) (relu?))
// Tile 128 x TN, BK=16, 256 worker threads, double-buffered smem.
// B stored in smem as duplicated f32x2 pairs (no per-kk pack needed).
// flags: bit0 = relu, bit1 = accumulate into existing C.
// ============================================================================
template<int TN> struct GemmSmem {
    float As[2][16][128];
    u64   Bs[2][16][TN];
};

template<int TN>
__device__ __forceinline__ void gemm_store_stage(
    GemmSmem<TN>* sm, int s, int ar, int akc, int bn, int bkc,
    const float4& ra0, const float4& ra1, const float4& rb0, const float4& rb1)
{
    sm->As[s][akc+0][ar] = ra0.x;
    sm->As[s][akc+1][ar] = ra0.y;
    sm->As[s][akc+2][ar] = ra0.z;
    sm->As[s][akc+3][ar] = ra0.w;
    sm->As[s][akc+4][ar] = ra1.x;
    sm->As[s][akc+5][ar] = ra1.y;
    sm->As[s][akc+6][ar] = ra1.z;
    sm->As[s][akc+7][ar] = ra1.w;
    sm->Bs[s][bkc+0][bn] = pack2(rb0.x, rb0.x);
    sm->Bs[s][bkc+1][bn] = pack2(rb0.y, rb0.y);
    sm->Bs[s][bkc+2][bn] = pack2(rb0.z, rb0.z);
    sm->Bs[s][bkc+3][bn] = pack2(rb0.w, rb0.w);
    if (TN == 128) {
        sm->Bs[s][bkc+4][bn] = pack2(rb1.x, rb1.x);
        sm->Bs[s][bkc+5][bn] = pack2(rb1.y, rb1.y);
        sm->Bs[s][bkc+6][bn] = pack2(rb1.z, rb1.z);
        sm->Bs[s][bkc+7][bn] = pack2(rb1.w, rb1.w);
    }
}

template<int TN>
__device__ __forceinline__ void gemm_body(
    GemmSmem<TN>* sm,
    const float* __restrict__ A, int lda,
    const float* __restrict__ W, int ldw,
    const float* __restrict__ bias,
    float* __restrict__ C, int ldc, int K,
    int m0, int n0, int flags, int tid, bool worker)
{
    const int CP = TN / 16;          // cols per thread (8 or 4)
    const int niter = K >> 4;
    const int ar = tid & 127, akc = (tid >> 7) << 3;
    int bn, bkc;
    if (TN == 128) { bn = tid & 127; bkc = (tid >> 7) << 3; }
    else           { bn = tid & 63;  bkc = (tid >> 6) << 2; }
    const int ty = tid >> 4, tx = tid & 15;

    const float* ap = A + (size_t)(m0 + ar) * lda + akc;
    const float* bp = W + (size_t)(n0 + bn) * ldw + bkc;

    float4 ra0, ra1, rb0, rb1;
    if (worker) {
        ra0 = *(const float4*)ap;
        ra1 = *(const float4*)(ap + 4);
        rb0 = *(const float4*)bp;
        if (TN == 128) rb1 = *(const float4*)(bp + 4);
        gemm_store_stage<TN>(sm, 0, ar, akc, bn, bkc, ra0, ra1, rb0, rb1);
    }
    __syncthreads();

    u64 acc[4][CP];
#pragma unroll
    for (int p = 0; p < 4; ++p)
#pragma unroll
        for (int c = 0; c < CP; ++c) acc[p][c] = 0ull;

    for (int it = 0; it < niter; ++it) {
        const int s = it & 1;
        if (worker && it + 1 < niter) {
            ap += 16; bp += 16;
            ra0 = *(const float4*)ap;
            ra1 = *(const float4*)(ap + 4);
            rb0 = *(const float4*)bp;
            if (TN == 128) rb1 = *(const float4*)(bp + 4);
        }
        if (worker) {
#pragma unroll
            for (int kk = 0; kk < 16; ++kk) {
                ulonglong2 a01 = *(const ulonglong2*)&sm->As[s][kk][ty << 3];
                ulonglong2 a23 = *(const ulonglong2*)&sm->As[s][kk][(ty << 3) + 4];
                u64 av[4]; av[0]=a01.x; av[1]=a01.y; av[2]=a23.x; av[3]=a23.y;
                u64 bv[CP];
#pragma unroll
                for (int c = 0; c < CP; c += 2) {
                    ulonglong2 b2 = *(const ulonglong2*)&sm->Bs[s][kk][tx * CP + c];
                    bv[c] = b2.x; bv[c+1] = b2.y;
                }
#pragma unroll
                for (int p = 0; p < 4; ++p)
#pragma unroll
                    for (int c = 0; c < CP; ++c)
                        acc[p][c] = ffma2(av[p], bv[c], acc[p][c]);
            }
        }
        if (it + 1 < niter) {
            if (worker)
                gemm_store_stage<TN>(sm, s ^ 1, ar, akc, bn, bkc, ra0, ra1, rb0, rb1);
            __syncthreads();
        }
    }
    if (!worker) return;

    float bvv[CP];
#pragma unroll
    for (int c = 0; c < CP; ++c) bvv[c] = bias ? bias[n0 + tx*CP + c] : 0.f;

#pragma unroll
    for (int p = 0; p < 4; ++p) {
#pragma unroll
        for (int half = 0; half < 2; ++half) {
            const int row = m0 + (ty << 3) + (p << 1) + half;
            float* cp = C + (size_t)row * ldc + n0 + tx * CP;
            float v[CP];
#pragma unroll
            for (int c = 0; c < CP; ++c)
                v[c] = (half ? hi2(acc[p][c]) : lo2(acc[p][c])) + bvv[c];
            if (flags & 2) {
#pragma unroll
                for (int c4 = 0; c4 < CP; c4 += 4) {
                    float4 o = *(const float4*)&cp[c4];
                    v[c4+0] += o.x; v[c4+1] += o.y; v[c4+2] += o.z; v[c4+3] += o.w;
                }
            }
            if (flags & 1) {
#pragma unroll
                for (int c = 0; c < CP; ++c) v[c] = fmaxf(v[c], 0.f);
            }
#pragma unroll
            for (int c4 = 0; c4 < CP; c4 += 4)
                *(float4*)&cp[c4] = make_float4(v[c4], v[c4+1], v[c4+2], v[c4+3]);
        }
    }
}

template<int TN>
__global__ void __launch_bounds__(256) k_gemm(
    const float* __restrict__ A, int lda,
    const float* __restrict__ W, int ldw,
    const float* __restrict__ bias,
    float* __restrict__ C, int ldc, int K, int flags)
{
    __shared__ GemmSmem<TN> sm;
    gemm_body<TN>(&sm, A, lda, W, ldw, bias, C, ldc, K,
                  blockIdx.y * 128, blockIdx.x * TN, flags, threadIdx.x, true);
}

// ---------------- per-token attention scalars (Ar, As) ----------------------
__global__ void __launch_bounds__(256) k_scal(const float* __restrict__ R,
                                              const float* __restrict__ S) {
    int warp = (blockIdx.x * blockDim.x + threadIdx.x) >> 5;
    int lane = threadIdx.x & 31;
    if (warp >= NTOK) return;
    int tok = warp;
    const float* pr = g_processed + (size_t)tok * NP;
    float aa = 0.f, ab = 0.f, ac = 0.f;
#pragma unroll
    for (int p = lane; p < NP; p += 32) {
        float pv = pr[p];
        aa = fmaf(pv, g_wa[p], aa);
        ab = fmaf(pv, g_wb[p], ab);
        ac = fmaf(pv, g_wc[p], ac);
    }
#pragma unroll
    for (int o = 16; o; o >>= 1) {
        aa += __shfl_down_sync(0xffffffffu, aa, o);
        ab += __shfl_down_sync(0xffffffffu, ab, o);
        ac += __shfl_down_sync(0xffffffffu, ac, o);
    }
    if (lane == 0) {
        aa += g_cc[0]; ab += g_cc[1]; ac += g_cc[2];
        int t = tok & (NT - 1);
        int s = tok >> 11;          // b*4+m
        int m = s & 3;
        float sc[3], Ro[3], So[3];
        int n = 0;
        for (int j = 0; j < NM; j++) {
            if (j == m) continue;
            size_t idx = ((size_t)s * NM + j) * NT + t;
            float r = R[idx], sv = S[idx];
            Ro[n] = r; So[n] = sv;
            sc[n] = (fmaf(aa, r, fmaf(ab, sv, ac))) * 0.125f;
            n++;
        }
        float mx = fmaxf(sc[0], fmaxf(sc[1], sc[2]));
        float e0 = expf(sc[0] - mx), e1 = expf(sc[1] - mx), e2 = expf(sc[2] - mx);
        float inv = 1.f / (e0 + e1 + e2);
        g_scal[2*tok]   = (e0*Ro[0] + e1*Ro[1] + e2*Ro[2]) * inv;
        g_scal[2*tok+1] = (e0*So[0] + e1*So[1] + e2*So[2]) * inv;
    }
}

// ============================================================================
// Fused kernel: blocks 0..31 run the GRU scan (1 seq each, 32 SMs);
// blocks 32.. run mlp1a GEMM tiles (hid = processed @ w1[:, :256]^T + b1,
// NO relu) on the otherwise-idle 116 SMs, hidden under the GRU's latency.
// ============================================================================
struct GruSmem {
    float hbuf[NH];
    float exch[3*NH];
    float exch_xn[NH];
    float su[512], sar[512], sas[512];
};
union FusedSmem {
    GemmSmem<64> gemm;
    GruSmem gru;
};

__global__ void __launch_bounds__(384, 1) k_fused(
    const float* __restrict__ U, const float* __restrict__ whh,
    const float* __restrict__ bhh,
    const float* __restrict__ w1, const float* __restrict__ b1)
{
    __shared__ FusedSmem smem;
    const int i = threadIdx.x;

    if (blockIdx.x >= 32) {
        // ---- mlp1a GEMM tile ----
        int tile = blockIdx.x - 32;          // 0..1535
        int tn = tile % 3, tm = tile / 3;
        gemm_body<64>(&smem.gemm, g_processed, NP, w1, NCOMB, b1,
                      g_hid, NMLP, NP, tm * 128, tn * 64, 0, i, i < 256);
        return;
    }

    // ---- GRU scan for sequence blockIdx.x ----
    const int s = blockIdx.x;

    u64 w2r[NH/2];
    const u64* wp = (const u64*)(whh + (size_t)i * NH);
#pragma unroll
    for (int k = 0; k < NH/2; k++) w2r[k] = wp[k];
    const float bb = bhh[i];
    const float c0 = g_c0[i], c1 = g_c1[i], c2 = g_c2[i], c3 = g_c3[i];

    if (i < NH) smem.gru.hbuf[i] = 0.f;
    const size_t base = (size_t)s * NT;
    float* outp = g_rus + base * NH + i;   // valid only for i < NH

    for (int t0 = 0; t0 < NT; t0 += 512) {
        __syncthreads();
        for (int j = i; j < 512; j += 384) {
            size_t g = base + t0 + j;
            smem.gru.su[j]  = U[g];
            smem.gru.sar[j] = g_scal[2*g];
            smem.gru.sas[j] = g_scal[2*g + 1];
        }
        __syncthreads();
        for (int tt = 0; tt < 512; tt++) {
            float xt = fmaf(smem.gru.su[tt], c0,
                       fmaf(smem.gru.sar[tt], c1,
                       fmaf(smem.gru.sas[tt], c2, c3)));
            u64 a0 = 0ull, a1 = 0ull;
#pragma unroll
            for (int k = 0; k < NH/4; k++) {
                ulonglong2 hv = *(const ulonglong2*)&smem.gru.hbuf[k << 2];
                a0 = ffma2(w2r[2*k],   hv.x, a0);
                a1 = ffma2(w2r[2*k+1], hv.y, a1);
            }
            float acc = bb + ((lo2(a0) + hi2(a0)) + (lo2(a1) + hi2(a1)));
            if (i < 2*NH) smem.gru.exch[i] = acc + xt;
            else { smem.gru.exch[i] = acc; smem.gru.exch_xn[i - 2*NH] = xt; }
            __syncthreads();
            if (i < NH) {
                float r = __fdividef(1.f, 1.f + __expf(-smem.gru.exch[i]));
                float z = __fdividef(1.f, 1.f + __expf(-smem.gru.exch[NH + i]));
                float nn = tanhf(fmaf(r, smem.gru.exch[2*NH + i], smem.gru.exch_xn[i]));
                float hnew = fmaf(z, smem.gru.hbuf[i] - nn, nn);
                outp[(size_t)(t0 + tt) * NH] = hnew;
                smem.gru.hbuf[i] = hnew;
            }
            __syncthreads();
        }
    }
}

// ---------------- final 192 -> 16 projection --------------------------------
__global__ void __launch_bounds__(256) k_mlp2(const float* __restrict__ w2,
                                              const float* __restrict__ b2,
                                              float* __restrict__ out) {
    __shared__ __align__(16) float sh[16][196];
    __shared__ __align__(16) float sw[16][196];
    const int tid = threadIdx.x;
    const int tok0 = blockIdx.x << 4;
    for (int idx = tid; idx < 16*NMLP; idx += 256) {
        int e = idx / NMLP, k = idx - e*NMLP;
        sw[e][k] = w2[idx];
    }
    for (int idx = tid; idx < 16*NMLP; idx += 256) {
        int r = idx / NMLP, k = idx - r*NMLP;
        sh[r][k] = g_hid[(size_t)(tok0 + r) * NMLP + k];
    }
    __syncthreads();
    const int e = tid & 15, r = tid >> 4;
    float acc = b2[e];
#pragma unroll
    for (int k = 0; k < NMLP; k += 4) {
        float4 hv = *(const float4*)&sh[r][k];
        float4 wv = *(const float4*)&sw[e][k];
        acc = fmaf(hv.x, wv.x, acc);
        acc = fmaf(hv.y, wv.y, acc);
        acc = fmaf(hv.z, wv.z, acc);
        acc = fmaf(hv.w, wv.w, acc);
    }
    out[(size_t)(tok0 + r) * NX + e] = acc;
}

// ---------------- launch ----------------------------------------------------
extern "C" void kernel_launch(void* const* d_in, const int* in_sizes, int n_in,
                              void* d_out, int out_size) {
    const float* emb  = (const float*)d_in[0];
    const float* U    = (const float*)d_in[1];
    const float* R    = (const float*)d_in[2];
    const float* S    = (const float*)d_in[3];
    const float* tp_w = (const float*)d_in[4];
    const float* tp_b = (const float*)d_in[5];
    const float* q_w  = (const float*)d_in[6];
    const float* q_b  = (const float*)d_in[7];
    const float* k_w  = (const float*)d_in[8];
    const float* k_b  = (const float*)d_in[9];
    const float* v_w  = (const float*)d_in[10];
    const float* v_b  = (const float*)d_in[11];
    const float* wih  = (const float*)d_in[12];
    const float* whh  = (const float*)d_in[13];
    const float* bih  = (const float*)d_in[14];
    const float* bhh  = (const float*)d_in[15];
    const float* w1   = (const float*)d_in[16];
    const float* b1   = (const float*)d_in[17];
    const float* w2   = (const float*)d_in[18];
    const float* b2   = (const float*)d_in[19];
    float* out = (float*)d_out;

    float *processed, *hid, *rus;
    cudaGetSymbolAddress((void**)&processed, g_processed);
    cudaGetSymbolAddress((void**)&hid, g_hid);
    cudaGetSymbolAddress((void**)&rus, g_rus);

    k_pre<<<1, 384>>>(q_w, q_b, k_w, k_b, wih, bih, v_w, v_b);
    // processed = relu(emb @ tp_w^T + tp_b)
    k_gemm<128><<<dim3(NP/128, NTOK/128), 256>>>(emb, NE, tp_w, NE, tp_b,
                                                 processed, NP, NE, 1);
    k_scal<<<NTOK/8, 256>>>(R, S);
    // GRU (32 blocks) + mlp1a (hid = processed @ w1[:, :256]^T + b1)
    k_fused<<<32 + (NTOK/128)*(NMLP/64), 384>>>(U, whh, bhh, w1, b1);
    // hid = relu(hid + rus @ w1[:, 256:384]^T)
    k_gemm<64><<<dim3(NMLP/64, NTOK/128), 256>>>(rus, NH, w1 + NP, NCOMB,
                                                 nullptr, hid, NMLP, NH, 3);
    k_mlp2<<<NTOK/16, 256>>>(w2, b2, out);
}

// round 4
// speedup vs baseline: 2.5187x; 2.5187x over previous
#include <cuda_runtime.h>
#include <math.h>

typedef unsigned long long u64;

#define NB 8
#define NM 4
#define NT 2048
#define NE 768
#define NP 256
#define NKD 64
#define NVD 64
#define NH 128
#define NX 16
#define NCOMB 384
#define NMLP 192
#define NTOK (NB*NM*NT)   /* 65536 */

// ---------------- scratch ----------------------------------------------------
__device__ float g_processed[(size_t)NTOK*NP];
__device__ float g_hid[(size_t)NTOK*NMLP];
__device__ float g_scal[(size_t)NTOK*2];
__device__ float g_rus[(size_t)NTOK*NH];
__device__ float g_wa[NP], g_wb[NP], g_wc[NP];
__device__ float g_cc[3];
__device__ float g_c0[3*NH], g_c1[3*NH], g_c2[3*NH], g_c3[3*NH];

// ---------------- f32x2 helpers ---------------------------------------------
__device__ __forceinline__ u64 ffma2(u64 a, u64 b, u64 c) {
    u64 d;
    asm("fma.rn.f32x2 %0, %1, %2, %3;" : "=l"(d) : "l"(a), "l"(b), "l"(c));
    return d;
}
__device__ __forceinline__ u64 pack2(float x, float y) {
    u64 d;
    asm("mov.b64 %0, {%1, %2};" : "=l"(d) : "f"(x), "f"(y));
    return d;
}
__device__ __forceinline__ float lo2(u64 v) { return __uint_as_float((unsigned)v); }
__device__ __forceinline__ float hi2(u64 v) { return __uint_as_float((unsigned)(v >> 32)); }

// ---------------- precompute folded weight vectors ---------------------------
__global__ void __launch_bounds__(384) k_pre(
                      const float* __restrict__ qw, const float* __restrict__ qb,
                      const float* __restrict__ kw, const float* __restrict__ kb,
                      const float* __restrict__ wih, const float* __restrict__ bih,
                      const float* __restrict__ vw, const float* __restrict__ vb) {
    int i = threadIdx.x;
    if (i < NP) {
        float a = 0.f, b = 0.f, c = 0.f;
#pragma unroll 4
        for (int k = 0; k < NKD; k++) {
            float q = qw[k*NP + i];
            a = fmaf(q, kw[2*k], a);
            b = fmaf(q, kw[2*k+1], b);
            c = fmaf(q, kb[k], c);
        }
        g_wa[i] = a; g_wb[i] = b; g_wc[i] = c;
    }
    if (i == 0) {
        float a = 0.f, b = 0.f, c = 0.f;
#pragma unroll 4
        for (int k = 0; k < NKD; k++) {
            float q = qb[k];
            a = fmaf(q, kw[2*k], a);
            b = fmaf(q, kw[2*k+1], b);
            c = fmaf(q, kb[k], c);
        }
        g_cc[0] = a; g_cc[1] = b; g_cc[2] = c;
    }
    if (i < 3*NH) {
        const float* wr = wih + (size_t)i*(1 + NVD);
        float c1 = 0.f, c2 = 0.f, c3 = bih[i];
#pragma unroll 4
        for (int v = 0; v < NVD; v++) {
            float w = wr[1 + v];
            c1 = fmaf(w, vw[2*v], c1);
            c2 = fmaf(w, vw[2*v+1], c2);
            c3 = fmaf(w, vb[v], c3);
        }
        g_c0[i] = wr[0]; g_c1[i] = c1; g_c2[i] = c2; g_c3[i] = c3;
    }
}

// ============================================================================
// SGEMM: C = relu(A @ W^T + bias).  A rows split: cols [0,K1) from A1
// (row stride lda1), cols [K1,K) from A2 (row stride lda2). W [N x K] rowmaj.
// Tile 128 x 64, BK=16, 256 threads, 8x4 micro-tile (f32x2 pairs of rows),
// double-buffered smem, one __syncthreads per K-slab.
//   A smem: [16][132] padded (store conflict 2-way, reads broadcast, aligned)
//   B smem: [16][64] floats (float4 reads conflict-free; pack2 in regs)
// ============================================================================
#define APAD 132
struct GemmSmem {
    float As[2][16][APAD];
    float Bs[2][16][64];
};

__global__ void __launch_bounds__(256) k_gemm(
    const float* __restrict__ A1, int lda1, int K1,
    const float* __restrict__ A2, int lda2,
    const float* __restrict__ W, int ldw,
    const float* __restrict__ bias,
    float* __restrict__ C, int ldc, int K)
{
    __shared__ GemmSmem sm;
    const int m0 = blockIdx.y << 7, n0 = blockIdx.x << 6;
    const int tid = threadIdx.x;
    const int tx = tid & 15, ty = tid >> 4;
    // A load map: float4 idx v=tid -> row v>>2 (0..63), kcol (v&3)*4; 2nd f4 row+64
    const int ar  = tid >> 2;
    const int akc = (tid & 3) << 2;
    // B load map: 64 rows x 16 k, 1 float4/thread
    const int bn  = tid & 63;
    const int bkc = (tid >> 6) << 2;

    const float* pA1a = A1 + (size_t)(m0 + ar) * lda1 + akc;
    const float* pA1b = pA1a + (size_t)64 * lda1;
    const float* pA2a = A2 + (size_t)(m0 + ar) * lda2 + akc;
    const float* pA2b = pA2a + (size_t)64 * lda2;
    const float* pB   = W + (size_t)(n0 + bn) * ldw + bkc;

    const int niter = K >> 4;

    float4 ra0, ra1, rb;
    // prologue: k0 = 0 (always from A1)
    ra0 = *(const float4*)pA1a;
    ra1 = *(const float4*)pA1b;
    rb  = *(const float4*)pB;
    {
        sm.As[0][akc+0][ar] = ra0.x; sm.As[0][akc+1][ar] = ra0.y;
        sm.As[0][akc+2][ar] = ra0.z; sm.As[0][akc+3][ar] = ra0.w;
        sm.As[0][akc+0][ar+64] = ra1.x; sm.As[0][akc+1][ar+64] = ra1.y;
        sm.As[0][akc+2][ar+64] = ra1.z; sm.As[0][akc+3][ar+64] = ra1.w;
        sm.Bs[0][bkc+0][bn] = rb.x; sm.Bs[0][bkc+1][bn] = rb.y;
        sm.Bs[0][bkc+2][bn] = rb.z; sm.Bs[0][bkc+3][bn] = rb.w;
    }
    __syncthreads();

    u64 acc[4][4];
#pragma unroll
    for (int p = 0; p < 4; ++p)
#pragma unroll
        for (int c = 0; c < 4; ++c) acc[p][c] = 0ull;

    for (int it = 0; it < niter; ++it) {
        const int s = it & 1;
        const bool more = (it + 1 < niter);
        if (more) {
            const int k0 = (it + 1) << 4;
            if (k0 < K1) {
                ra0 = *(const float4*)(pA1a + k0);
                ra1 = *(const float4*)(pA1b + k0);
            } else {
                ra0 = *(const float4*)(pA2a + (k0 - K1));
                ra1 = *(const float4*)(pA2b + (k0 - K1));
            }
            rb = *(const float4*)(pB + k0);
        }
#pragma unroll
        for (int kk = 0; kk < 16; ++kk) {
            ulonglong2 a01 = *(const ulonglong2*)&sm.As[s][kk][ty << 3];
            ulonglong2 a23 = *(const ulonglong2*)&sm.As[s][kk][(ty << 3) + 4];
            float4 b4 = *(const float4*)&sm.Bs[s][kk][tx << 2];
            u64 bb0 = pack2(b4.x, b4.x);
            u64 bb1 = pack2(b4.y, b4.y);
            u64 bb2 = pack2(b4.z, b4.z);
            u64 bb3 = pack2(b4.w, b4.w);
            acc[0][0] = ffma2(a01.x, bb0, acc[0][0]);
            acc[1][0] = ffma2(a01.y, bb0, acc[1][0]);
            acc[2][0] = ffma2(a23.x, bb0, acc[2][0]);
            acc[3][0] = ffma2(a23.y, bb0, acc[3][0]);
            acc[0][1] = ffma2(a01.x, bb1, acc[0][1]);
            acc[1][1] = ffma2(a01.y, bb1, acc[1][1]);
            acc[2][1] = ffma2(a23.x, bb1, acc[2][1]);
            acc[3][1] = ffma2(a23.y, bb1, acc[3][1]);
            acc[0][2] = ffma2(a01.x, bb2, acc[0][2]);
            acc[1][2] = ffma2(a01.y, bb2, acc[1][2]);
            acc[2][2] = ffma2(a23.x, bb2, acc[2][2]);
            acc[3][2] = ffma2(a23.y, bb2, acc[3][2]);
            acc[0][3] = ffma2(a01.x, bb3, acc[0][3]);
            acc[1][3] = ffma2(a01.y, bb3, acc[1][3]);
            acc[2][3] = ffma2(a23.x, bb3, acc[2][3]);
            acc[3][3] = ffma2(a23.y, bb3, acc[3][3]);
        }
        if (more) {
            const int d = s ^ 1;
            sm.As[d][akc+0][ar] = ra0.x; sm.As[d][akc+1][ar] = ra0.y;
            sm.As[d][akc+2][ar] = ra0.z; sm.As[d][akc+3][ar] = ra0.w;
            sm.As[d][akc+0][ar+64] = ra1.x; sm.As[d][akc+1][ar+64] = ra1.y;
            sm.As[d][akc+2][ar+64] = ra1.z; sm.As[d][akc+3][ar+64] = ra1.w;
            sm.Bs[d][bkc+0][bn] = rb.x; sm.Bs[d][bkc+1][bn] = rb.y;
            sm.Bs[d][bkc+2][bn] = rb.z; sm.Bs[d][bkc+3][bn] = rb.w;
            __syncthreads();
        }
    }

    float4 bias4 = *(const float4*)&bias[n0 + (tx << 2)];
#pragma unroll
    for (int p = 0; p < 4; ++p) {
#pragma unroll
        for (int half = 0; half < 2; ++half) {
            const int row = m0 + (ty << 3) + (p << 1) + half;
            float4 v;
            v.x = (half ? hi2(acc[p][0]) : lo2(acc[p][0])) + bias4.x;
            v.y = (half ? hi2(acc[p][1]) : lo2(acc[p][1])) + bias4.y;
            v.z = (half ? hi2(acc[p][2]) : lo2(acc[p][2])) + bias4.z;
            v.w = (half ? hi2(acc[p][3]) : lo2(acc[p][3])) + bias4.w;
            v.x = fmaxf(v.x, 0.f); v.y = fmaxf(v.y, 0.f);
            v.z = fmaxf(v.z, 0.f); v.w = fmaxf(v.w, 0.f);
            *(float4*)&C[(size_t)row * ldc + n0 + (tx << 2)] = v;
        }
    }
}

// ---------------- per-token attention scalars (Ar, As) ----------------------
__global__ void __launch_bounds__(256) k_scal(const float* __restrict__ R,
                                              const float* __restrict__ S) {
    int warp = (blockIdx.x * blockDim.x + threadIdx.x) >> 5;
    int lane = threadIdx.x & 31;
    if (warp >= NTOK) return;
    int tok = warp;
    const float* pr = g_processed + (size_t)tok * NP;
    float aa = 0.f, ab = 0.f, ac = 0.f;
#pragma unroll
    for (int p = lane; p < NP; p += 32) {
        float pv = pr[p];
        aa = fmaf(pv, g_wa[p], aa);
        ab = fmaf(pv, g_wb[p], ab);
        ac = fmaf(pv, g_wc[p], ac);
    }
#pragma unroll
    for (int o = 16; o; o >>= 1) {
        aa += __shfl_down_sync(0xffffffffu, aa, o);
        ab += __shfl_down_sync(0xffffffffu, ab, o);
        ac += __shfl_down_sync(0xffffffffu, ac, o);
    }
    if (lane == 0) {
        aa += g_cc[0]; ab += g_cc[1]; ac += g_cc[2];
        int t = tok & (NT - 1);
        int s = tok >> 11;          // b*4+m
        int m = s & 3;
        float sc[3], Ro[3], So[3];
        int n = 0;
        for (int j = 0; j < NM; j++) {
            if (j == m) continue;
            size_t idx = ((size_t)s * NM + j) * NT + t;
            float r = R[idx], sv = S[idx];
            Ro[n] = r; So[n] = sv;
            sc[n] = (fmaf(aa, r, fmaf(ab, sv, ac))) * 0.125f;
            n++;
        }
        float mx = fmaxf(sc[0], fmaxf(sc[1], sc[2]));
        float e0 = expf(sc[0] - mx), e1 = expf(sc[1] - mx), e2 = expf(sc[2] - mx);
        float inv = 1.f / (e0 + e1 + e2);
        g_scal[2*tok]   = (e0*Ro[0] + e1*Ro[1] + e2*Ro[2]) * inv;
        g_scal[2*tok+1] = (e0*So[0] + e1*So[1] + e2*So[2]) * inv;
    }
}

// ---------------- GRU scan: one block per sequence (32 blocks) --------------
__global__ void __launch_bounds__(384, 1) k_gru(const float* __restrict__ U,
                                                const float* __restrict__ whh,
                                                const float* __restrict__ bhh) {
    __shared__ __align__(16) float hbuf[NH];
    __shared__ float exch[3*NH];
    __shared__ float exch_xn[NH];
    __shared__ float su[512], sar[512], sas[512];
    const int s = blockIdx.x;
    const int i = threadIdx.x;

    u64 w2r[NH/2];
    const u64* wp = (const u64*)(whh + (size_t)i * NH);
#pragma unroll
    for (int k = 0; k < NH/2; k++) w2r[k] = wp[k];
    const float bb = bhh[i];
    const float c0 = g_c0[i], c1 = g_c1[i], c2 = g_c2[i], c3 = g_c3[i];

    if (i < NH) hbuf[i] = 0.f;
    const size_t base = (size_t)s * NT;
    float* outp = g_rus + base * NH + i;   // valid only for i < NH

    for (int t0 = 0; t0 < NT; t0 += 512) {
        __syncthreads();
        for (int j = i; j < 512; j += 384) {
            size_t g = base + t0 + j;
            su[j]  = U[g];
            sar[j] = g_scal[2*g];
            sas[j] = g_scal[2*g + 1];
        }
        __syncthreads();
        for (int tt = 0; tt < 512; tt++) {
            float xt = fmaf(su[tt], c0, fmaf(sar[tt], c1, fmaf(sas[tt], c2, c3)));
            u64 a0 = 0ull, a1 = 0ull;
#pragma unroll
            for (int k = 0; k < NH/4; k++) {
                ulonglong2 hv = *(const ulonglong2*)&hbuf[k << 2];
                a0 = ffma2(w2r[2*k],   hv.x, a0);
                a1 = ffma2(w2r[2*k+1], hv.y, a1);
            }
            float acc = bb + ((lo2(a0) + hi2(a0)) + (lo2(a1) + hi2(a1)));
            if (i < 2*NH) exch[i] = acc + xt;
            else { exch[i] = acc; exch_xn[i - 2*NH] = xt; }
            __syncthreads();
            if (i < NH) {
                float r = __fdividef(1.f, 1.f + __expf(-exch[i]));
                float z = __fdividef(1.f, 1.f + __expf(-exch[NH + i]));
                float nn = tanhf(fmaf(r, exch[2*NH + i], exch_xn[i]));
                float hnew = fmaf(z, hbuf[i] - nn, nn);   // (1-z)*n + z*h
                outp[(size_t)(t0 + tt) * NH] = hnew;
                hbuf[i] = hnew;
            }
            __syncthreads();
        }
    }
}

// ---------------- final 192 -> 16 projection --------------------------------
__global__ void __launch_bounds__(256) k_mlp2(const float* __restrict__ w2,
                                              const float* __restrict__ b2,
                                              float* __restrict__ out) {
    __shared__ __align__(16) float sh[16][196];
    __shared__ __align__(16) float sw[16][196];
    const int tid = threadIdx.x;
    const int tok0 = blockIdx.x << 4;
    for (int idx = tid; idx < 16*NMLP; idx += 256) {
        int e = idx / NMLP, k = idx - e*NMLP;
        sw[e][k] = w2[idx];
    }
    for (int idx = tid; idx < 16*NMLP; idx += 256) {
        int r = idx / NMLP, k = idx - r*NMLP;
        sh[r][k] = g_hid[(size_t)(tok0 + r) * NMLP + k];
    }
    __syncthreads();
    const int e = tid & 15, r = tid >> 4;
    float acc = b2[e];
#pragma unroll
    for (int k = 0; k < NMLP; k += 4) {
        float4 hv = *(const float4*)&sh[r][k];
        float4 wv = *(const float4*)&sw[e][k];
        acc = fmaf(hv.x, wv.x, acc);
        acc = fmaf(hv.y, wv.y, acc);
        acc = fmaf(hv.z, wv.z, acc);
        acc = fmaf(hv.w, wv.w, acc);
    }
    out[(size_t)(tok0 + r) * NX + e] = acc;
}

// ---------------- launch ----------------------------------------------------
extern "C" void kernel_launch(void* const* d_in, const int* in_sizes, int n_in,
                              void* d_out, int out_size) {
    const float* emb  = (const float*)d_in[0];
    const float* U    = (const float*)d_in[1];
    const float* R    = (const float*)d_in[2];
    const float* S    = (const float*)d_in[3];
    const float* tp_w = (const float*)d_in[4];
    const float* tp_b = (const float*)d_in[5];
    const float* q_w  = (const float*)d_in[6];
    const float* q_b  = (const float*)d_in[7];
    const float* k_w  = (const float*)d_in[8];
    const float* k_b  = (const float*)d_in[9];
    const float* v_w  = (const float*)d_in[10];
    const float* v_b  = (const float*)d_in[11];
    const float* wih  = (const float*)d_in[12];
    const float* whh  = (const float*)d_in[13];
    const float* bih  = (const float*)d_in[14];
    const float* bhh  = (const float*)d_in[15];
    const float* w1   = (const float*)d_in[16];
    const float* b1   = (const float*)d_in[17];
    const float* w2   = (const float*)d_in[18];
    const float* b2   = (const float*)d_in[19];
    float* out = (float*)d_out;

    float *processed, *hid, *rus;
    cudaGetSymbolAddress((void**)&processed, g_processed);
    cudaGetSymbolAddress((void**)&hid, g_hid);
    cudaGetSymbolAddress((void**)&rus, g_rus);

    k_pre<<<1, 384>>>(q_w, q_b, k_w, k_b, wih, bih, v_w, v_b);
    // processed = relu(emb @ tp_w^T + tp_b)
    k_gemm<<<dim3(NP/64, NTOK/128), 256>>>(emb, NE, NE, emb, NE,
                                           tp_w, NE, tp_b,
                                           processed, NP, NE);
    k_scal<<<NTOK/8, 256>>>(R, S);
    k_gru<<<NB*NM, 384>>>(U, whh, bhh);
    // hid = relu([processed | rus] @ w1^T + b1)  (single pass, split A)
    k_gemm<<<dim3(NMLP/64, NTOK/128), 256>>>(processed, NP, NP, rus, NH,
                                             w1, NCOMB, b1,
                                             hid, NMLP, NCOMB);
    k_mlp2<<<NTOK/16, 256>>>(w2, b2, out);
}